// round 12
// baseline (speedup 1.0000x reference)
#include <cuda_runtime.h>
#include <cuda_fp16.h>
#include <stdint.h>

#define B_TOK 8192
#define DIM   2048
#define NEXP  8

#define BM 128
#define BN 128
#define BK 128
#define NKC (DIM / BK)          // 16
#define NNT (DIM / BN)          // 16
#define MAXTILES 72
#define NCW 8                   // compute warps
#define GTHREADS (NCW * 32 + 64)    // + 2 converter warps = 320

#define TILE_A 32768            // 128m x 128k fp16, 2 k-subtiles of 16KB, SW128
#define TILE_B 32768            // 128k x 128n fp16, 2 n-subtiles of 16KB, SW128
#define STAGE_SZ (TILE_A + TILE_B)   // 65536
#define OFF_B TILE_A
#define OFF_MB (2 * STAGE_SZ)        // 131072
#define OFF_ROWS (OFF_MB + 64)
#define SMEM_REQ (OFF_ROWS + 512 + 1024)

#define NTB 32
#define ITEMS_PER_KC (NEXP * NNT + MAXTILES)   // 128 B-tiles + 72 A-tiles = 200
#define TOTAL_ITEMS (NKC * ITEMS_PER_KC)       // 3200

// -------- device scratch --------
__device__ int d_bh[NTB][NEXP];
__device__ int d_boff[NTB][NEXP];
__device__ int d_poff[NEXP + 1];
__device__ int d_is64 = 1;           // monotone latch (input-fixed -> deterministic)
__device__ int d_done = 0;
__device__ int d_work = 0;
__device__ int d_perm[MAXTILES * 128];

__device__ volatile int f_a[MAXTILES * NKC];          // 1152
__device__ volatile int f_b[NEXP * NNT * NKC];        // 2048

__device__ __align__(128) char g_xa[(size_t)MAXTILES * NKC * TILE_A];       // 36 MB
__device__ __align__(128) char g_wb[(size_t)NEXP * NNT * NKC * TILE_B];     // 64 MB

// ======================= helpers =======================
__device__ __forceinline__ uint32_t smem_u32(const void* p) {
    uint32_t a;
    asm("{ .reg .u64 t; cvta.to.shared.u64 t, %1; cvt.u32.u64 %0, t; }" : "=r"(a) : "l"(p));
    return a;
}
__device__ __forceinline__ uint32_t sw128(uint32_t off) { return off ^ ((off >> 3) & 0x70); }

__device__ __forceinline__ void ldsm_x4(uint32_t* r, uint32_t addr) {
    asm volatile("ldmatrix.sync.aligned.m8n8.x4.shared.b16 {%0,%1,%2,%3}, [%4];"
                 : "=r"(r[0]), "=r"(r[1]), "=r"(r[2]), "=r"(r[3]) : "r"(addr));
}
__device__ __forceinline__ void ldsm_x4_t(uint32_t* r, uint32_t addr) {
    asm volatile("ldmatrix.sync.aligned.m8n8.x4.trans.shared.b16 {%0,%1,%2,%3}, [%4];"
                 : "=r"(r[0]), "=r"(r[1]), "=r"(r[2]), "=r"(r[3]) : "r"(addr));
}
__device__ __forceinline__ void mma16816(float* d, const uint32_t* a, uint32_t b0, uint32_t b1) {
    asm volatile(
        "mma.sync.aligned.m16n8k16.row.col.f32.f16.f16.f32 "
        "{%0,%1,%2,%3}, {%4,%5,%6,%7}, {%8,%9}, {%0,%1,%2,%3};"
        : "+f"(d[0]), "+f"(d[1]), "+f"(d[2]), "+f"(d[3])
        : "r"(a[0]), "r"(a[1]), "r"(a[2]), "r"(a[3]), "r"(b0), "r"(b1));
}
__device__ __forceinline__ void bulk_g2s(uint32_t dst, const void* src, uint32_t bytes, uint32_t mbar) {
    asm volatile(
        "{\n\t.reg .u64 g;\n\tcvta.to.global.u64 g, %1;\n\t"
        "cp.async.bulk.shared::cluster.global.mbarrier::complete_tx::bytes [%0], [g], %2, [%3];\n\t}"
        :: "r"(dst), "l"(src), "r"(bytes), "r"(mbar) : "memory");
}
#define MBARRIER_INIT(addr, cnt) \
    asm volatile("mbarrier.init.shared.b64 [%0], %1;" :: "r"((uint32_t)(addr)), "r"((uint32_t)(cnt)) : "memory")
#define MBARRIER_EXPECT_TX(addr, tx) \
    asm volatile("mbarrier.arrive.expect_tx.shared.b64 _, [%0], %1;" :: "r"((uint32_t)(addr)), "r"((uint32_t)(tx)) : "memory")
#define MBARRIER_WAIT_PARITY(addr, par) do { \
    uint32_t _m = (uint32_t)(addr); uint32_t _p = (uint32_t)(par); uint32_t _done; \
    asm volatile("{\n\t.reg .pred p;\n\t" \
        "mbarrier.try_wait.parity.acquire.cta.shared::cta.b64 p, [%1], %2;\n\t" \
        "selp.b32 %0, 1, 0, p;\n\t}" : "=r"(_done) : "r"(_m), "r"(_p) : "memory"); \
    if (!_done) { \
        asm volatile("{\n\t.reg .pred P1;\n\t" \
            "WL_%=:\n\tmbarrier.try_wait.parity.acquire.cta.shared::cta.b64 P1, [%0], %1, 0x989680;\n\t" \
            "@P1 bra.uni WD_%=;\n\tbra.uni WL_%=;\n\tWD_%=:\n\t}" \
            :: "r"(_m), "r"(_p) : "memory"); \
    } \
} while (0)
#define BAR_COMPUTE() asm volatile("bar.sync 1, %0;" :: "n"(NCW * 32) : "memory")

__device__ __forceinline__ int expert_of(const int* v, int i) { return d_is64 ? v[2 * i] : v[i]; }

// ======================= K0: detect + reset =======================
__global__ void k0_reset_detect(const int* __restrict__ v32) {
    int i = blockIdx.x * 256 + threadIdx.x;          // 0..8191
    if ((i & 1) && v32[i] != 0) d_is64 = 0;
    for (int j = i; j < MAXTILES * 128; j += 8192) d_perm[j] = -1;
    if (i < MAXTILES * NKC) f_a[i] = 0;
    if (i < NEXP * NNT * NKC) f_b[i] = 0;
    if (i == 0) { d_done = 0; d_work = 0; }
}

// ======================= K1: per-block hist + global scan =======================
__global__ void k1_hist_scan(const int* __restrict__ v32) {
    __shared__ int h[NEXP];
    const int t = threadIdx.x;
    const int b = blockIdx.x;
    if (t < NEXP) h[t] = 0;
    __syncthreads();
    int e = expert_of(v32, b * 256 + t);
    if (e >= 0 && e < NEXP) atomicAdd(&h[e], 1);
    __syncthreads();
    if (t < NEXP) d_bh[b][t] = h[t];
    __threadfence();
    if (t == 0) {
        int r = atomicAdd(&d_done, 1);
        if (r == NTB - 1) {
            int tot[NEXP];
            for (int ee = 0; ee < NEXP; ee++) {
                int s = 0;
                for (int bb = 0; bb < NTB; bb++) s += d_bh[bb][ee];
                tot[ee] = s;
            }
            int pacc = 0;
            d_poff[0] = 0;
            for (int ee = 0; ee < NEXP; ee++) {
                int base = pacc;
                pacc += ((tot[ee] + 127) / 128) * 128;
                d_poff[ee + 1] = pacc;
                int run = base;
                for (int bb = 0; bb < NTB; bb++) { d_boff[bb][ee] = run; run += d_bh[bb][ee]; }
            }
            d_done = 0;
            __threadfence();
        }
    }
}

// ======================= K2: deterministic scatter =======================
__global__ void k2_scatter(const int* __restrict__ v32) {
    __shared__ short se[256];
    const int t = threadIdx.x;
    const int tb = blockIdx.x;
    int e = expert_of(v32, tb * 256 + t);
    se[t] = (short)e;
    __syncthreads();
    int rank = 0;
    for (int j = 0; j < t; j++) rank += (se[j] == (short)e);
    if (e >= 0 && e < NEXP)
        d_perm[d_boff[tb][e] + rank] = tb * 256 + t;
}

// ======================= converter-warp tile conversion =======================
// B tile (e,nt,kc): [128k x 128n] fp16, 2 n-subtiles of (128k x 64n), SW128.
__device__ void convert_b_tile(const float* __restrict__ W, int e, int nt, int kc, int lane) {
    const float* Wb = W + ((size_t)e * DIM + kc * BK) * DIM + nt * BN;
    char* dst = g_wb + ((size_t)((e * NNT + nt) * NKC + kc)) * TILE_B;
#pragma unroll 4
    for (int g = lane; g < 2048; g += 32) {
        int k = g >> 4, c = g & 15;                  // c covers 8 n
        const float4* s4 = (const float4*)(Wb + (size_t)k * DIM + c * 8);
        float4 w0 = s4[0];
        float4 w1 = s4[1];
        __half2 h0 = __floats2half2_rn(w0.x, w0.y);
        __half2 h1 = __floats2half2_rn(w0.z, w0.w);
        __half2 h2 = __floats2half2_rn(w1.x, w1.y);
        __half2 h3 = __floats2half2_rn(w1.z, w1.w);
        uint4 val;
        val.x = *(uint32_t*)&h0; val.y = *(uint32_t*)&h1;
        val.z = *(uint32_t*)&h2; val.w = *(uint32_t*)&h3;
        *(uint4*)(dst + ((c >> 3) << 14) + sw128((uint32_t)(k * 128 + (c & 7) * 16))) = val;
    }
}
// A tile (mt,kc): [128m x 128k] fp16, 2 k-subtiles of (128m x 64k), SW128.
__device__ void convert_a_tile(const float* __restrict__ x, int mt, int kc, int lane) {
    char* dst = g_xa + ((size_t)(mt * NKC + kc)) * TILE_A;
#pragma unroll 4
    for (int h = lane; h < 4096; h += 32) {
        int r = h >> 5, Fl = h & 31;                 // Fl covers 4 k
        int grow = d_perm[mt * 128 + r];
        uint2 hv = make_uint2(0u, 0u);
        if (grow >= 0) {
            float4 w = *(const float4*)(x + (size_t)grow * DIM + kc * BK + Fl * 4);
            __half2 h0 = __floats2half2_rn(w.x, w.y);
            __half2 h1 = __floats2half2_rn(w.z, w.w);
            hv.x = *(uint32_t*)&h0; hv.y = *(uint32_t*)&h1;
        }
        *(uint2*)(dst + ((Fl >> 4) << 14) + sw128((uint32_t)(r * 128 + (Fl & 15) * 8))) = hv;
    }
}

// ======================= K3: fused convert + grouped GEMM =======================
__global__ void __launch_bounds__(GTHREADS, 1)
k_mega(const float* __restrict__ x, const float* __restrict__ W,
       const float* __restrict__ bias, float* __restrict__ out)
{
    const int nt = blockIdx.x;           // 0..15
    const int mt = blockIdx.y;           // 0..71
    const int m0p = mt * BM;

    const int tid = threadIdx.x;
    const int wid = tid >> 5;
    const int lane = tid & 31;

    // ================= converter warps: global kc-ordered queue =================
    if (wid >= NCW) {
        const int lim = d_poff[NEXP];
        for (;;) {
            int w = 0;
            if (lane == 0) w = atomicAdd(&d_work, 1);
            w = __shfl_sync(0xffffffffu, w, 0);
            if (w >= TOTAL_ITEMS) break;
            const int kc = w / ITEMS_PER_KC;
            const int r = w - kc * ITEMS_PER_KC;
            if (r < NEXP * NNT) {
                convert_b_tile(W, r >> 4, r & 15, kc, lane);
                __threadfence();
                __syncwarp();
                if (lane == 0) f_b[r * NKC + kc] = 2;
            } else {
                const int amt = r - NEXP * NNT;
                if (amt * BM < lim) convert_a_tile(x, amt, kc, lane);
                __threadfence();
                __syncwarp();
                if (lane == 0) f_a[amt * NKC + kc] = 2;
            }
        }
        return;
    }

    // ================= compute warps =================
    if (m0p >= d_poff[NEXP]) return;
    int e = 0;
#pragma unroll
    for (int i = 0; i < NEXP; i++) if (m0p >= d_poff[i + 1]) e = i + 1;
    const int n0 = nt * BN;
    const int eb = (e * NNT + nt) * NKC;
    const int ab = mt * NKC;

    extern __shared__ char smraw[];
    const uint32_t A0 = (smem_u32(smraw) + 1023u) & ~1023u;
    char* sbase = smraw + (A0 - smem_u32(smraw));
    const uint32_t mb = A0 + OFF_MB;
    int* rows = (int*)(sbase + OFF_ROWS);

    const int warp_m = wid >> 2;     // 0..1 -> 64 m-rows
    const int warp_n = wid & 3;      // 0..3 -> 32 n-cols

    if (tid < BM) rows[tid] = d_perm[m0p + tid];
    if (tid == 0) {
        MBARRIER_INIT(mb, 1);
        MBARRIER_INIT(mb + 8, 1);
    }
    BAR_COMPUTE();

    // chunk 0: spin flags, issue
    if (tid == 0) {
        while (f_a[ab] != 2 || f_b[eb] != 2) __nanosleep(64);
        MBARRIER_EXPECT_TX(mb, (uint32_t)STAGE_SZ);
        bulk_g2s(A0, g_xa + (size_t)ab * TILE_A, TILE_A, mb);
        bulk_g2s(A0 + OFF_B, g_wb + (size_t)eb * TILE_B, TILE_B, mb);
    }

    float acc[4][4][4];
#pragma unroll
    for (int i = 0; i < 4; i++)
#pragma unroll
        for (int j = 0; j < 4; j++)
#pragma unroll
            for (int q = 0; q < 4; q++) acc[i][j][q] = 0.0f;

    const int lrow = lane & 15;
    const int lc16 = (lane >> 4) << 4;
    uint32_t a0off[4];
#pragma unroll
    for (int i = 0; i < 4; i++)
        a0off[i] = sw128((uint32_t)((warp_m * 64 + i * 16 + lrow) * 128 + lc16));
    const int blk = lane >> 3;
    const int ng = blk & 1;
    const int base_k = (blk >> 1) * 8 + (lane & 7);
    uint32_t b0off[2];
#pragma unroll
    for (int g = 0; g < 2; g++) {
        int nn = (warp_n & 1) * 32 + g * 16 + ng * 8;
        b0off[g] = ((uint32_t)(warp_n >> 1) << 14)
                 + sw128((uint32_t)(base_k * 128 + nn * 2));
    }

    for (int c = 0; c < NKC; c++) {
        const int s = c & 1;
        if (tid == 0 && c + 1 < NKC) {
            const int nc = c + 1;
            while (f_a[ab + nc] != 2 || f_b[eb + nc] != 2) __nanosleep(64);
            uint32_t bar = mb + (nc & 1) * 8;
            MBARRIER_EXPECT_TX(bar, (uint32_t)STAGE_SZ);
            uint32_t sb = A0 + (nc & 1) * STAGE_SZ;
            bulk_g2s(sb, g_xa + (size_t)(ab + nc) * TILE_A, TILE_A, bar);
            bulk_g2s(sb + OFF_B, g_wb + (size_t)(eb + nc) * TILE_B, TILE_B, bar);
        }

        MBARRIER_WAIT_PARITY(mb + s * 8, (c >> 1) & 1);

        const uint32_t aA = A0 + s * STAGE_SZ;
        const uint32_t aB = aA + OFF_B;
#pragma unroll
        for (int ks = 0; ks < 8; ks++) {
            uint32_t bf[2][4];
            const uint32_t bofs = aB + ((uint32_t)ks << 11);
#pragma unroll
            for (int g = 0; g < 2; g++) ldsm_x4_t(bf[g], bofs + b0off[g]);
            const uint32_t asub = aA + ((uint32_t)(ks >> 2) << 14);
            const uint32_t akx = (uint32_t)((ks & 3) << 5);
#pragma unroll
            for (int i = 0; i < 4; i++) {
                uint32_t af[4];
                ldsm_x4(af, asub + (a0off[i] ^ akx));
#pragma unroll
                for (int j = 0; j < 4; j++)
                    mma16816(acc[i][j], af, bf[j >> 1][j & 1], bf[j >> 1][(j & 1) + 2]);
            }
        }
        BAR_COMPUTE();
    }

    // epilogue: add bias, scatter rows
    const float* be = bias + (size_t)e * DIM;
#pragma unroll
    for (int i = 0; i < 4; i++) {
#pragma unroll
        for (int half = 0; half < 2; half++) {
            int mloc = warp_m * 64 + i * 16 + (lane >> 2) + half * 8;
            int grow = rows[mloc];
            if (grow < 0) continue;
            float* orow = out + (size_t)grow * DIM;
#pragma unroll
            for (int j = 0; j < 4; j++) {
                int col = n0 + warp_n * 32 + j * 8 + (lane & 3) * 2;
                float2 bb = *(const float2*)(be + col);
                float2 o;
                o.x = acc[i][j][half * 2 + 0] + bb.x;
                o.y = acc[i][j][half * 2 + 1] + bb.y;
                *(float2*)(orow + col) = o;
            }
        }
    }
}

// ======================= host =======================
extern "C" void kernel_launch(void* const* d_in, const int* in_sizes, int n_in,
                              void* d_out, int out_size)
{
    const float* x = nullptr;
    const float* W = nullptr;
    const float* b = nullptr;
    const void* idx = nullptr;
    for (int i = 0; i < n_in; i++) {
        long long sz = in_sizes[i];
        if      (sz == (long long)B_TOK * DIM)      x = (const float*)d_in[i];
        else if (sz == (long long)NEXP * DIM * DIM) W = (const float*)d_in[i];
        else if (sz == (long long)NEXP * DIM)       b = (const float*)d_in[i];
        else if (sz == (long long)B_TOK)            idx = d_in[i];
    }
    float* out = (float*)d_out;
    const int* v32 = (const int*)idx;

    cudaFuncSetAttribute(k_mega, cudaFuncAttributeMaxDynamicSharedMemorySize, SMEM_REQ);

    k0_reset_detect<<<32, 256>>>(v32);               // launch 1
    k1_hist_scan<<<NTB, 256>>>(v32);                 // launch 2
    k2_scatter<<<NTB, 256>>>(v32);                   // launch 3
    dim3 ggrid(NNT, MAXTILES);                       // (16, 72) = 1152 CTAs
    k_mega<<<ggrid, GTHREADS, SMEM_REQ>>>(x, W, b, out);   // launch 4 (ncu target)
}

// round 13
// speedup vs baseline: 1.8345x; 1.8345x over previous
#include <cuda_runtime.h>
#include <cuda_fp16.h>
#include <stdint.h>

#define B_TOK 8192
#define DIM   2048
#define NEXP  8

#define BM 128
#define BN 128
#define BK 128
#define NKC (DIM / BK)          // 16
#define NNT (DIM / BN)          // 16
#define MAXTILES 72
#define GTHREADS 256            // 8 compute warps

#define TILE_A 32768            // 128m x 128k fp16, 2 k-subtiles of 16KB, SW128
#define TILE_B 32768            // 128k x 128n fp16, 2 n-subtiles of 16KB, SW128
#define STAGE_SZ (TILE_A + TILE_B)   // 65536
#define OFF_B TILE_A
#define OFF_MB (2 * STAGE_SZ)        // 131072
#define OFF_ROWS (OFF_MB + 64)
#define SMEM_REQ (OFF_ROWS + 512 + 1024)

#define NTB 32

// -------- device scratch --------
__device__ int d_bh[NTB][NEXP];
__device__ int d_boff[NTB][NEXP];
__device__ int d_poff[NEXP + 1];
__device__ int d_is64 = 1;           // monotone latch
__device__ int d_done = 0;
__device__ int d_perm[MAXTILES * 128];

__device__ __align__(128) char g_xa[(size_t)MAXTILES * NKC * TILE_A];       // 36 MB
__device__ __align__(128) char g_wb[(size_t)NEXP * NNT * NKC * TILE_B];     // 64 MB

// ======================= helpers =======================
__device__ __forceinline__ uint32_t smem_u32(const void* p) {
    uint32_t a;
    asm("{ .reg .u64 t; cvta.to.shared.u64 t, %1; cvt.u32.u64 %0, t; }" : "=r"(a) : "l"(p));
    return a;
}
__device__ __forceinline__ uint32_t sw128(uint32_t off) { return off ^ ((off >> 3) & 0x70); }

__device__ __forceinline__ void ldsm_x4(uint32_t* r, uint32_t addr) {
    asm volatile("ldmatrix.sync.aligned.m8n8.x4.shared.b16 {%0,%1,%2,%3}, [%4];"
                 : "=r"(r[0]), "=r"(r[1]), "=r"(r[2]), "=r"(r[3]) : "r"(addr));
}
__device__ __forceinline__ void ldsm_x4_t(uint32_t* r, uint32_t addr) {
    asm volatile("ldmatrix.sync.aligned.m8n8.x4.trans.shared.b16 {%0,%1,%2,%3}, [%4];"
                 : "=r"(r[0]), "=r"(r[1]), "=r"(r[2]), "=r"(r[3]) : "r"(addr));
}
// fp16-accumulate HMMA: D(f16x2 x2) = A*B + D
__device__ __forceinline__ void mma16816h(uint32_t* d, const uint32_t* a, uint32_t b0, uint32_t b1) {
    asm volatile(
        "mma.sync.aligned.m16n8k16.row.col.f16.f16.f16.f16 "
        "{%0,%1}, {%2,%3,%4,%5}, {%6,%7}, {%0,%1};"
        : "+r"(d[0]), "+r"(d[1])
        : "r"(a[0]), "r"(a[1]), "r"(a[2]), "r"(a[3]), "r"(b0), "r"(b1));
}
__device__ __forceinline__ void promote4(float* a4, uint32_t h0, uint32_t h1) {
    float2 f0 = __half22float2(*(__half2*)&h0);
    float2 f1 = __half22float2(*(__half2*)&h1);
    a4[0] += f0.x; a4[1] += f0.y; a4[2] += f1.x; a4[3] += f1.y;
}
__device__ __forceinline__ void bulk_g2s(uint32_t dst, const void* src, uint32_t bytes, uint32_t mbar) {
    asm volatile(
        "{\n\t.reg .u64 g;\n\tcvta.to.global.u64 g, %1;\n\t"
        "cp.async.bulk.shared::cluster.global.mbarrier::complete_tx::bytes [%0], [g], %2, [%3];\n\t}"
        :: "r"(dst), "l"(src), "r"(bytes), "r"(mbar) : "memory");
}
#define MBARRIER_INIT(addr, cnt) \
    asm volatile("mbarrier.init.shared.b64 [%0], %1;" :: "r"((uint32_t)(addr)), "r"((uint32_t)(cnt)) : "memory")
#define MBARRIER_EXPECT_TX(addr, tx) \
    asm volatile("mbarrier.arrive.expect_tx.shared.b64 _, [%0], %1;" :: "r"((uint32_t)(addr)), "r"((uint32_t)(tx)) : "memory")
#define MBARRIER_WAIT_PARITY(addr, par) do { \
    uint32_t _m = (uint32_t)(addr); uint32_t _p = (uint32_t)(par); uint32_t _done; \
    asm volatile("{\n\t.reg .pred p;\n\t" \
        "mbarrier.try_wait.parity.acquire.cta.shared::cta.b64 p, [%1], %2;\n\t" \
        "selp.b32 %0, 1, 0, p;\n\t}" : "=r"(_done) : "r"(_m), "r"(_p) : "memory"); \
    if (!_done) { \
        asm volatile("{\n\t.reg .pred P1;\n\t" \
            "WL_%=:\n\tmbarrier.try_wait.parity.acquire.cta.shared::cta.b64 P1, [%0], %1, 0x989680;\n\t" \
            "@P1 bra.uni WD_%=;\n\tbra.uni WL_%=;\n\tWD_%=:\n\t}" \
            :: "r"(_m), "r"(_p) : "memory"); \
    } \
} while (0)

__device__ __forceinline__ int expert_of(const int* v, int i) { return d_is64 ? v[2 * i] : v[i]; }

// ======================= K1: convw (K-major, coalesced, no smem) + init + detect =======================
// B tile (e,nt,kc): [128k x 128n] fp16, 2 n-subtiles of (128k x 64n), SW128.
__global__ void k1_convw_init(const float* __restrict__ W, const int* __restrict__ v32) {
    const int bid = blockIdx.x + NNT * (blockIdx.y + NKC * blockIdx.z);  // 0..2047
    const int t = threadIdx.x;

    if (bid < 36) {
        int i = bid * 256 + t;
        if (i < MAXTILES * 128) d_perm[i] = -1;
        if (bid == 0 && t == 0) d_done = 0;
    }
    if (bid >= 64 && bid < 96) {
        int i = (bid - 64) * 256 + t;
        if ((i & 1) && v32[i] != 0) d_is64 = 0;
    }

    const int nt = blockIdx.x, kc = blockIdx.y, e = blockIdx.z;
    const float* Wb = W + ((size_t)e * DIM + kc * BK) * DIM + nt * BN;
    char* dst = g_wb + ((size_t)((e * NNT + nt) * NKC + kc)) * TILE_B;
#pragma unroll
    for (int i = 0; i < 8; i++) {
        int g = i * 256 + t;                 // 0..2047 granules of 32B (8 n)
        int k = g >> 4, c = g & 15;
        const float4* s4 = (const float4*)(Wb + (size_t)k * DIM + c * 8);
        float4 w0 = s4[0];
        float4 w1 = s4[1];
        __half2 h0 = __floats2half2_rn(w0.x, w0.y);
        __half2 h1 = __floats2half2_rn(w0.z, w0.w);
        __half2 h2 = __floats2half2_rn(w1.x, w1.y);
        __half2 h3 = __floats2half2_rn(w1.z, w1.w);
        uint4 val;
        val.x = *(uint32_t*)&h0; val.y = *(uint32_t*)&h1;
        val.z = *(uint32_t*)&h2; val.w = *(uint32_t*)&h3;
        *(uint4*)(dst + ((c >> 3) << 14) + sw128((uint32_t)(k * 128 + (c & 7) * 16))) = val;
    }
}

// ======================= K2: per-block hist + global scan =======================
__global__ void k2_hist_scan(const int* __restrict__ v32) {
    __shared__ int h[NEXP];
    const int t = threadIdx.x;
    const int b = blockIdx.x;
    if (t < NEXP) h[t] = 0;
    __syncthreads();
    int e = expert_of(v32, b * 256 + t);
    if (e >= 0 && e < NEXP) atomicAdd(&h[e], 1);
    __syncthreads();
    if (t < NEXP) d_bh[b][t] = h[t];
    __threadfence();
    if (t == 0) {
        int r = atomicAdd(&d_done, 1);
        if (r == NTB - 1) {
            int tot[NEXP];
            for (int ee = 0; ee < NEXP; ee++) {
                int s = 0;
                for (int bb = 0; bb < NTB; bb++) s += d_bh[bb][ee];
                tot[ee] = s;
            }
            int pacc = 0;
            d_poff[0] = 0;
            for (int ee = 0; ee < NEXP; ee++) {
                int base = pacc;
                pacc += ((tot[ee] + 127) / 128) * 128;
                d_poff[ee + 1] = pacc;
                int run = base;
                for (int bb = 0; bb < NTB; bb++) { d_boff[bb][ee] = run; run += d_bh[bb][ee]; }
            }
            d_done = 0;
            __threadfence();
        }
    }
}

// ======================= K3: deterministic scatter + convx =======================
// A tile (mt,kc): [128m x 128k] fp16, 2 k-subtiles of (128m x 64k), SW128.
__global__ void k3_scatter_convx(const int* __restrict__ v32, const float* __restrict__ x) {
    __shared__ short se[256];
    __shared__ int spos[256];
    const int t = threadIdx.x;
    const int tb = blockIdx.x, y = blockIdx.y;

    int e = expert_of(v32, tb * 256 + t);
    se[t] = (short)e;
    __syncthreads();
    int rank = 0;
    for (int j = 0; j < t; j++) rank += (se[j] == (short)e);
    int pos = (e >= 0 && e < NEXP) ? d_boff[tb][e] + rank : -1;
    spos[t] = pos;
    if (y == 0 && pos >= 0) d_perm[pos] = tb * 256 + t;
    __syncthreads();

    const int f = t & 63;
    const int jb = t >> 6;
    for (int rep = 0; rep < 64; rep++) {
        int j = rep * 4 + jb;
        int pos_j = spos[j];
        if (pos_j < 0) continue;
        float4 w = *(const float4*)(x + (size_t)(tb * 256 + j) * DIM + y * 256 + f * 4);
        __half2 h0 = __floats2half2_rn(w.x, w.y);
        __half2 h1 = __floats2half2_rn(w.z, w.w);
        uint2 hv;
        hv.x = *(uint32_t*)&h0; hv.y = *(uint32_t*)&h1;
        int tile = pos_j >> 7, r = pos_j & 127;
        int kc2  = y * 2 + (f >> 5);
        int ksub = (f >> 4) & 1;
        *(uint2*)(g_xa + ((size_t)tile * NKC + kc2) * TILE_A + (ksub << 14)
                  + sw128((uint32_t)(r * 128 + (f & 15) * 8))) = hv;
    }
}

// ======================= K4: grouped GEMM (fp16-acc split-K) =======================
__device__ __forceinline__ void issue_stage(uint32_t A0, uint32_t mb, int chunk, int stage,
                                            int mt, int e, int nt) {
    uint32_t bar = mb + stage * 8;
    MBARRIER_EXPECT_TX(bar, (uint32_t)STAGE_SZ);
    const char* asrc = g_xa + ((size_t)(mt * NKC + chunk)) * TILE_A;
    const char* bsrc = g_wb + ((size_t)((e * NNT + nt) * NKC + chunk)) * TILE_B;
    uint32_t sb = A0 + stage * STAGE_SZ;
    bulk_g2s(sb, asrc, TILE_A, bar);
    bulk_g2s(sb + OFF_B, bsrc, TILE_B, bar);
}

__global__ void __launch_bounds__(GTHREADS, 1)
k_gemm(const float* __restrict__ bias, float* __restrict__ out)
{
    const int nt = blockIdx.x;
    const int mt = blockIdx.y;
    const int m0p = mt * BM;
    if (m0p >= d_poff[NEXP]) return;
    int e = 0;
#pragma unroll
    for (int i = 0; i < NEXP; i++) if (m0p >= d_poff[i + 1]) e = i + 1;
    const int n0 = nt * BN;

    extern __shared__ char smraw[];
    const uint32_t A0 = (smem_u32(smraw) + 1023u) & ~1023u;
    char* sbase = smraw + (A0 - smem_u32(smraw));
    const uint32_t mb = A0 + OFF_MB;
    int* rows = (int*)(sbase + OFF_ROWS);

    const int tid = threadIdx.x;
    const int wid = tid >> 5;
    const int lane = tid & 31;
    const int warp_m = wid >> 2;     // 0..1 -> 64 m-rows
    const int warp_n = wid & 3;      // 0..3 -> 32 n-cols

    if (tid < BM) rows[tid] = d_perm[m0p + tid];
    if (tid == 0) {
        MBARRIER_INIT(mb, 1);
        MBARRIER_INIT(mb + 8, 1);
    }
    __syncthreads();

    if (tid == 0) issue_stage(A0, mb, 0, 0, mt, e, nt);

    float acc[4][4][4];
#pragma unroll
    for (int i = 0; i < 4; i++)
#pragma unroll
        for (int j = 0; j < 4; j++)
#pragma unroll
            for (int q = 0; q < 4; q++) acc[i][j][q] = 0.0f;

    const int lrow = lane & 15;
    const int lc16 = (lane >> 4) << 4;
    uint32_t a0off[4];
#pragma unroll
    for (int i = 0; i < 4; i++)
        a0off[i] = sw128((uint32_t)((warp_m * 64 + i * 16 + lrow) * 128 + lc16));
    const int blk = lane >> 3;
    const int ng = blk & 1;
    const int base_k = (blk >> 1) * 8 + (lane & 7);
    uint32_t b0off[2];
#pragma unroll
    for (int g = 0; g < 2; g++) {
        int nn = (warp_n & 1) * 32 + g * 16 + ng * 8;
        b0off[g] = ((uint32_t)(warp_n >> 1) << 14)
                 + sw128((uint32_t)(base_k * 128 + nn * 2));
    }

    for (int c = 0; c < NKC; c++) {
        const int s = c & 1;
        if (tid == 0 && c + 1 < NKC) issue_stage(A0, mb, c + 1, (c + 1) & 1, mt, e, nt);

        MBARRIER_WAIT_PARITY(mb + s * 8, (c >> 1) & 1);

        // fp16 chunk accumulators (zeroed each chunk)
        uint32_t hacc[4][4][2];
#pragma unroll
        for (int i = 0; i < 4; i++)
#pragma unroll
            for (int j = 0; j < 4; j++) { hacc[i][j][0] = 0u; hacc[i][j][1] = 0u; }

        const uint32_t aA = A0 + s * STAGE_SZ;
        const uint32_t aB = aA + OFF_B;
#pragma unroll
        for (int ks = 0; ks < 8; ks++) {
            uint32_t bf[2][4];
            const uint32_t bofs = aB + ((uint32_t)ks << 11);
#pragma unroll
            for (int g = 0; g < 2; g++) ldsm_x4_t(bf[g], bofs + b0off[g]);
            const uint32_t asub = aA + ((uint32_t)(ks >> 2) << 14);
            const uint32_t akx = (uint32_t)((ks & 3) << 5);
#pragma unroll
            for (int i = 0; i < 4; i++) {
                uint32_t af[4];
                ldsm_x4(af, asub + (a0off[i] ^ akx));
#pragma unroll
                for (int j = 0; j < 4; j++)
                    mma16816h(hacc[i][j], af, bf[j >> 1][j & 1], bf[j >> 1][(j & 1) + 2]);
            }
        }
        // promote chunk partials to fp32
#pragma unroll
        for (int i = 0; i < 4; i++)
#pragma unroll
            for (int j = 0; j < 4; j++)
                promote4(acc[i][j], hacc[i][j][0], hacc[i][j][1]);

        __syncthreads();
    }

    // epilogue: add bias, scatter rows
    const float* be = bias + (size_t)e * DIM;
#pragma unroll
    for (int i = 0; i < 4; i++) {
#pragma unroll
        for (int half = 0; half < 2; half++) {
            int mloc = warp_m * 64 + i * 16 + (lane >> 2) + half * 8;
            int grow = rows[mloc];
            if (grow < 0) continue;
            float* orow = out + (size_t)grow * DIM;
#pragma unroll
            for (int j = 0; j < 4; j++) {
                int col = n0 + warp_n * 32 + j * 8 + (lane & 3) * 2;
                float2 bb = *(const float2*)(be + col);
                float2 o;
                o.x = acc[i][j][half * 2 + 0] + bb.x;
                o.y = acc[i][j][half * 2 + 1] + bb.y;
                *(float2*)(orow + col) = o;
            }
        }
    }
}

// ======================= host =======================
extern "C" void kernel_launch(void* const* d_in, const int* in_sizes, int n_in,
                              void* d_out, int out_size)
{
    const float* x = nullptr;
    const float* W = nullptr;
    const float* b = nullptr;
    const void* idx = nullptr;
    for (int i = 0; i < n_in; i++) {
        long long sz = in_sizes[i];
        if      (sz == (long long)B_TOK * DIM)      x = (const float*)d_in[i];
        else if (sz == (long long)NEXP * DIM * DIM) W = (const float*)d_in[i];
        else if (sz == (long long)NEXP * DIM)       b = (const float*)d_in[i];
        else if (sz == (long long)B_TOK)            idx = d_in[i];
    }
    float* out = (float*)d_out;
    const int* v32 = (const int*)idx;

    cudaFuncSetAttribute(k_gemm, cudaFuncAttributeMaxDynamicSharedMemorySize, SMEM_REQ);

    dim3 wgrid(NNT, NKC, NEXP);                      // 2048 blocks
    k1_convw_init<<<wgrid, 256>>>(W, v32);           // launch 1
    k2_hist_scan<<<NTB, 256>>>(v32);                 // launch 2
    k3_scatter_convx<<<dim3(NTB, 8), 256>>>(v32, x); // launch 3
    dim3 ggrid(NNT, MAXTILES);                       // (16, 72) = 1152 CTAs
    k_gemm<<<ggrid, GTHREADS, SMEM_REQ>>>(b, out);   // launch 4 (ncu target)
}